// round 4
// baseline (speedup 1.0000x reference)
#include <cuda_runtime.h>
#include <math.h>

// Problem constants
#define B 32
#define S 2048
#define D 1024
#define MASK_PENALTY 100000000.0f

// Tiling
#define NSPLIT 8
#define WARPS 8
#define THREADS (WARPS * 32)
#define ROWS_PER_SPLIT (S / NSPLIT)             // 256
#define ROWS_PER_WARP (ROWS_PER_SPLIT / WARPS)  // 32 (== warp size, mask preload)

typedef unsigned long long ull;

// Scratch (allocation-free: __device__ globals, zero-init)
__device__ float g_m[B * NSPLIT];
__device__ float g_l[B * NSPLIT];
__device__ __align__(16) float g_acc[(size_t)B * NSPLIT * D];  // 1 MB
__device__ int g_cnt[B];  // zero-init; self-resetting each launch

// ---- packed f32x2 helpers (Blackwell) ----
__device__ __forceinline__ ull pk2(float lo, float hi) {
    ull r; asm("mov.b64 %0, {%1,%2};" : "=l"(r) : "f"(lo), "f"(hi)); return r;
}
__device__ __forceinline__ void upk2(ull v, float& lo, float& hi) {
    asm("mov.b64 {%0,%1}, %2;" : "=f"(lo), "=f"(hi) : "l"(v));
}
__device__ __forceinline__ ull fma2(ull a, ull b, ull c) {
    ull d; asm("fma.rn.f32x2 %0, %1, %2, %3;" : "=l"(d) : "l"(a), "l"(b), "l"(c)); return d;
}
__device__ __forceinline__ ull mul2(ull a, ull b) {
    ull d; asm("mul.rn.f32x2 %0, %1, %2;" : "=l"(d) : "l"(a), "l"(b)); return d;
}
__device__ __forceinline__ ull add2(ull a, ull b) {
    ull d; asm("add.rn.f32x2 %0, %1, %2;" : "=l"(d) : "l"(a), "l"(b)); return d;
}
// volatile 128-bit shared load as two u64 (volatile => NOT hoisted into regs)
__device__ __forceinline__ void lds128(unsigned saddr, ull& a, ull& b) {
    asm volatile("ld.shared.v2.u64 {%0,%1}, [%2];" : "=l"(a), "=l"(b) : "r"(saddr));
}
__device__ __forceinline__ unsigned smem_u32(const void* p) {
    unsigned a;
    asm("{ .reg .u64 t; cvta.to.shared.u64 t, %1; cvt.u32.u64 %0, t; }"
        : "=r"(a) : "l"(p));
    return a;
}

// ---------------------------------------------------------------------------
// Fused single-pass online-softmax attention, query staged in SMEM so the
// register budget (acc 32 + row 32 + locals) fits 3 CTAs/SM (24 warps).
// One warp per context row; each lane owns 32 of 1024 D-elements as 8x16B
// (offset 16B*(lane + 32*i), fully coalesced).
// 8 warp partials merge in smem -> 1 per CTA -> last CTA per batch merges.
// ---------------------------------------------------------------------------
__global__ void __launch_bounds__(THREADS, 3)
attn_fused(const float* __restrict__ target,
           const float* __restrict__ context,
           const float* __restrict__ mask,
           float* __restrict__ out)
{
    const int b     = blockIdx.x;
    const int split = blockIdx.y;
    const int w     = threadIdx.x >> 5;
    const int lane  = threadIdx.x & 31;

    __shared__ __align__(16) float sq[D];              // 4 KB query
    __shared__ float sm_[WARPS];
    __shared__ float sl_[WARPS];
    __shared__ __align__(16) ull sacc[WARPS][D / 2];   // 32 KB

    // Stage the query vector into shared memory (one float4 per thread)
    ((float4*)sq)[threadIdx.x] = ((const float4*)(target + (size_t)b * D))[threadIdx.x];
    __syncthreads();

    // Per-lane shared address of this lane's first 16B chunk
    const unsigned sq_base = smem_u32(sq) + 16u * (unsigned)lane;

    ull acc2[16];
#pragma unroll
    for (int i = 0; i < 16; i++) acc2[i] = 0ull;

    float m = -INFINITY;
    float l = 0.f;

    const int s0 = split * ROWS_PER_SPLIT + w * ROWS_PER_WARP;
    const float* cb = context + (size_t)b * S * D;

    // Preload this warp's 32 masks (one per lane), broadcast per row via shfl
    const float mkv = mask[(size_t)b * S + s0 + lane];

    for (int r = 0; r < ROWS_PER_WARP; r++) {
        const ulonglong2* row = (const ulonglong2*)(cb + (size_t)(s0 + r) * D);

        ull c2[16];
#pragma unroll
        for (int i = 0; i < 8; i++) {
            ulonglong2 v = row[lane + 32 * i];
            c2[2 * i] = v.x; c2[2 * i + 1] = v.y;
        }

        // packed dot with query read from smem (2 independent chains)
        ull d0 = 0ull, d1 = 0ull;
#pragma unroll
        for (int i = 0; i < 8; i++) {
            ull tq0, tq1;
            lds128(sq_base + 512u * i, tq0, tq1);
            d0 = fma2(c2[2 * i],     tq0, d0);
            d1 = fma2(c2[2 * i + 1], tq1, d1);
        }
        float a0, a1, a2, a3;
        upk2(d0, a0, a1); upk2(d1, a2, a3);
        float dot = (a0 + a1) + (a2 + a3);
#pragma unroll
        for (int off = 16; off > 0; off >>= 1)
            dot += __shfl_xor_sync(0xffffffffu, dot, off);

        const float mval = __shfl_sync(0xffffffffu, mkv, r);
        const float score = dot + (mval - 1.f) * MASK_PENALTY;

        // lazy-rescale online softmax (warp-uniform, rarely-taken branch)
        if (score > m) {
            const float sc = __expf(m - score);   // 0 on first iteration
            const ull sc2 = pk2(sc, sc);
            l *= sc;
#pragma unroll
            for (int i = 0; i < 16; i++) acc2[i] = mul2(acc2[i], sc2);
            m = score;
        }
        const float wgt = __expf(score - m);
        l += wgt;
        const ull w2 = pk2(wgt, wgt);
#pragma unroll
        for (int i = 0; i < 16; i++) acc2[i] = fma2(w2, c2[i], acc2[i]);
    }

    // ---- In-CTA merge of the 8 warp partials ----
    if (lane == 0) { sm_[w] = m; sl_[w] = l; }
    __syncthreads();

    float Mcta = -INFINITY;
#pragma unroll
    for (int i = 0; i < WARPS; i++) Mcta = fmaxf(Mcta, sm_[i]);

    const float f = __expf(m - Mcta);
    const ull f2 = pk2(f, f);
#pragma unroll
    for (int i = 0; i < 8; i++) {
        ulonglong2 v;
        v.x = mul2(acc2[2 * i], f2);
        v.y = mul2(acc2[2 * i + 1], f2);
        ((ulonglong2*)sacc[w])[lane + 32 * i] = v;
    }
    __syncthreads();

    // 256 threads sum across the 8 warps, write CTA partial
    const int pidx = b * NSPLIT + split;
    const int d2 = threadIdx.x;   // one ulonglong2 (4 floats) each
    ulonglong2 sum = ((const ulonglong2*)sacc[0])[d2];
#pragma unroll
    for (int i = 1; i < WARPS; i++) {
        const ulonglong2 v = ((const ulonglong2*)sacc[i])[d2];
        sum.x = add2(sum.x, v.x);
        sum.y = add2(sum.y, v.y);
    }
    ((ulonglong2*)(g_acc + (size_t)pidx * D))[d2] = sum;

    if (threadIdx.x == 0) {
        float L = 0.f;
#pragma unroll
        for (int i = 0; i < WARPS; i++)
            L += __expf(sm_[i] - Mcta) * sl_[i];
        g_m[pidx] = Mcta;
        g_l[pidx] = L;
    }

    // ---- Last CTA per batch merges the NSPLIT partials ----
    __threadfence();
    __syncthreads();
    __shared__ int isLast;
    if (threadIdx.x == 0)
        isLast = (atomicAdd(&g_cnt[b], 1) == NSPLIT - 1);
    __syncthreads();
    if (!isLast) return;
    __threadfence();  // acquire

    float pm[NSPLIT], pl[NSPLIT];
#pragma unroll
    for (int p = 0; p < NSPLIT; p++) {
        pm[p] = __ldcg(&g_m[b * NSPLIT + p]);
        pl[p] = __ldcg(&g_l[b * NSPLIT + p]);
    }
    float M = -INFINITY;
#pragma unroll
    for (int p = 0; p < NSPLIT; p++) M = fmaxf(M, pm[p]);
    float L = 0.f;
#pragma unroll
    for (int p = 0; p < NSPLIT; p++) L += __expf(pm[p] - M) * pl[p];
    const float Linv = 1.f / L;

    ulonglong2 a; a.x = 0ull; a.y = 0ull;
#pragma unroll
    for (int p = 0; p < NSPLIT; p++) {
        const float fp = __expf(pm[p] - M);
        const ull fp2 = pk2(fp, fp);
        const ulonglong2 v =
            __ldcg((const ulonglong2*)(g_acc + (size_t)(b * NSPLIT + p) * D) + d2);
        a.x = fma2(fp2, v.x, a.x);
        a.y = fma2(fp2, v.y, a.y);
    }
    const ull li2 = pk2(Linv, Linv);
    a.x = mul2(a.x, li2);
    a.y = mul2(a.y, li2);
    ((ulonglong2*)(out + (size_t)b * D))[d2] = a;

    if (threadIdx.x == 0) atomicExch(&g_cnt[b], 0);
}

extern "C" void kernel_launch(void* const* d_in, const int* in_sizes, int n_in,
                              void* d_out, int out_size)
{
    const float* target  = (const float*)d_in[0];  // [B, D]
    const float* context = (const float*)d_in[1];  // [B, S, D]
    const float* mask    = (const float*)d_in[2];  // [B, S]
    float* out = (float*)d_out;                    // [B, D]

    dim3 grid(B, NSPLIT);
    attn_fused<<<grid, THREADS>>>(target, context, mask, out);
}

// round 6
// speedup vs baseline: 1.3486x; 1.3486x over previous
#include <cuda_runtime.h>
#include <math.h>

// Problem constants
#define B 32
#define S 2048
#define D 1024
#define MASK_PENALTY 100000000.0f

// Tiling
#define NSPLIT 8
#define WARPS 8
#define THREADS (WARPS * 32)
#define ROWS_PER_SPLIT (S / NSPLIT)             // 256
#define ROWS_PER_WARP (ROWS_PER_SPLIT / WARPS)  // 32 (== warp size, mask preload)

#define ROW_BYTES (D * 4)                       // 4096
#define STAGE_BYTES (WARPS * 2 * ROW_BYTES)     // 64 KB double buffer

// Scratch (allocation-free: __device__ globals, zero-init)
__device__ float g_m[B * NSPLIT];
__device__ float g_l[B * NSPLIT];
__device__ __align__(16) float g_acc[(size_t)B * NSPLIT * D];  // 1 MB
__device__ int g_cnt[B];  // zero-init; self-resets each launch

__device__ __forceinline__ void cp_async16(unsigned saddr, const void* gaddr) {
    asm volatile("cp.async.cg.shared.global [%0], [%1], 16;"
                 :: "r"(saddr), "l"(gaddr));
}
__device__ __forceinline__ void cp_commit() {
    asm volatile("cp.async.commit_group;");
}
template <int N>
__device__ __forceinline__ void cp_wait() {
    asm volatile("cp.async.wait_group %0;" :: "n"(N));
}

// ---------------------------------------------------------------------------
// Fused single-pass online-softmax attention with a cp.async double-buffered
// mainloop. One warp per context row; each lane owns 32 of the 1024
// D-elements (8 x 16B chunks at byte offset 16*lane + 512*i). Each lane
// stages exactly its own chunks with cp.async.cg, so loads for future rows
// stay in flight through the serial (reduce/exp) window of the current row.
// 8 warp partials merge in smem (stage buffer reused) -> 1 per CTA ->
// last CTA per batch merges the NSPLIT split-partials and writes the output.
// ---------------------------------------------------------------------------
__global__ void __launch_bounds__(THREADS, 2)
attn_fused(const float* __restrict__ target,
           const float* __restrict__ context,
           const float* __restrict__ mask,
           float* __restrict__ out)
{
    extern __shared__ __align__(16) char stage[];   // 64 KB

    const int b     = blockIdx.x;
    const int split = blockIdx.y;
    const int w     = threadIdx.x >> 5;
    const int lane  = threadIdx.x & 31;

    // Lane's slice of the query vector (registers)
    const float4* tg = (const float4*)(target + (size_t)b * D);
    float4 t[8];
#pragma unroll
    for (int i = 0; i < 8; i++) t[i] = tg[lane + 32 * i];

    float4 acc[8];
#pragma unroll
    for (int i = 0; i < 8; i++) acc[i] = make_float4(0.f, 0.f, 0.f, 0.f);

    float m = -INFINITY;
    float l = 0.f;

    const int s0 = split * ROWS_PER_SPLIT + w * ROWS_PER_WARP;
    const char* cb = (const char*)(context + (size_t)b * S * D);

    // This warp's double-buffer slots
    char* wslot = stage + w * (2 * ROW_BYTES);
    const unsigned sbase =
        (unsigned)__cvta_generic_to_shared(wslot) + 16u * (unsigned)lane;

    // Preload this warp's 32 masks (one per lane), broadcast per row via shfl
    const float mkv = mask[(size_t)b * S + s0 + lane];

    // Prologue: stage rows 0 and 1
#pragma unroll
    for (int p = 0; p < 2; p++) {
        const char* g = cb + (size_t)(s0 + p) * ROW_BYTES + 16u * lane;
#pragma unroll
        for (int i = 0; i < 8; i++)
            cp_async16(sbase + p * ROW_BYTES + 512 * i, g + 512 * i);
        cp_commit();
    }

    for (int r = 0; r < ROWS_PER_WARP; r++) {
        // Wait for row r's stage (last iter: drain everything)
        if (r == ROWS_PER_WARP - 1) cp_wait<0>(); else cp_wait<1>();

        const int slot = r & 1;
        const float4* sp = (const float4*)(wslot + slot * ROW_BYTES);
        float4 c[8];
#pragma unroll
        for (int i = 0; i < 8; i++) c[i] = sp[lane + 32 * i];

        // Immediately refill this slot with row r+2 (loads overlap compute)
        if (r + 2 < ROWS_PER_WARP) {
            const char* g = cb + (size_t)(s0 + r + 2) * ROW_BYTES + 16u * lane;
#pragma unroll
            for (int i = 0; i < 8; i++)
                cp_async16(sbase + slot * ROW_BYTES + 512 * i, g + 512 * i);
            cp_commit();
        }

        // dot(context_row, target) for this lane's slice (2 chains)
        float d0 = 0.f, d1 = 0.f;
#pragma unroll
        for (int i = 0; i < 8; i++) {
            d0 = fmaf(c[i].x, t[i].x, d0);
            d1 = fmaf(c[i].y, t[i].y, d1);
            d0 = fmaf(c[i].z, t[i].z, d0);
            d1 = fmaf(c[i].w, t[i].w, d1);
        }
        float dot = d0 + d1;
#pragma unroll
        for (int off = 16; off > 0; off >>= 1)
            dot += __shfl_xor_sync(0xffffffffu, dot, off);

        const float mval = __shfl_sync(0xffffffffu, mkv, r);
        const float score = dot + (mval - 1.f) * MASK_PENALTY;

        // online softmax update
        const float mnew  = fmaxf(m, score);
        const float scale = __expf(m - mnew);     // 0 on first iter
        const float wgt   = __expf(score - mnew);
        l = l * scale + wgt;
#pragma unroll
        for (int i = 0; i < 8; i++) {
            acc[i].x = fmaf(acc[i].x, scale, wgt * c[i].x);
            acc[i].y = fmaf(acc[i].y, scale, wgt * c[i].y);
            acc[i].z = fmaf(acc[i].z, scale, wgt * c[i].z);
            acc[i].w = fmaf(acc[i].w, scale, wgt * c[i].w);
        }
        m = mnew;
    }

    // ---- In-CTA merge of the 8 warp partials (stage buffer reused) ----
    __shared__ float sm_[WARPS];
    __shared__ float sl_[WARPS];

    if (lane == 0) { sm_[w] = m; sl_[w] = l; }
    __syncthreads();   // all warps done with their stage slots

    float Mcta = -INFINITY;
#pragma unroll
    for (int i = 0; i < WARPS; i++) Mcta = fmaxf(Mcta, sm_[i]);

    float4* sacc = (float4*)stage;   // [WARPS][D/4] = 32 KB within 64 KB
    const float f = __expf(m - Mcta);
#pragma unroll
    for (int i = 0; i < 8; i++) {
        float4 a = acc[i];
        a.x *= f; a.y *= f; a.z *= f; a.w *= f;
        sacc[w * (D / 4) + lane + 32 * i] = a;
    }
    __syncthreads();

    // 256 threads sum across the 8 warps, write CTA partial
    const int pidx = b * NSPLIT + split;
    const int d4 = threadIdx.x;
    float4 sum = sacc[d4];
#pragma unroll
    for (int i = 1; i < WARPS; i++) {
        const float4 v = sacc[i * (D / 4) + d4];
        sum.x += v.x; sum.y += v.y; sum.z += v.z; sum.w += v.w;
    }
    ((float4*)(g_acc + (size_t)pidx * D))[d4] = sum;

    if (threadIdx.x == 0) {
        float L = 0.f;
#pragma unroll
        for (int i = 0; i < WARPS; i++)
            L += __expf(sm_[i] - Mcta) * sl_[i];
        g_m[pidx] = Mcta;
        g_l[pidx] = L;
    }

    // ---- Last CTA per batch merges the NSPLIT partials ----
    __threadfence();
    __syncthreads();
    __shared__ int isLast;
    if (threadIdx.x == 0)
        isLast = (atomicAdd(&g_cnt[b], 1) == NSPLIT - 1);
    __syncthreads();
    if (!isLast) return;
    __threadfence();  // acquire

    float pm[NSPLIT], pl[NSPLIT];
#pragma unroll
    for (int p = 0; p < NSPLIT; p++) {
        pm[p] = __ldcg(&g_m[b * NSPLIT + p]);
        pl[p] = __ldcg(&g_l[b * NSPLIT + p]);
    }
    float M = -INFINITY;
#pragma unroll
    for (int p = 0; p < NSPLIT; p++) M = fmaxf(M, pm[p]);
    float L = 0.f;
#pragma unroll
    for (int p = 0; p < NSPLIT; p++) L += __expf(pm[p] - M) * pl[p];
    const float Linv = 1.f / L;

    float4 a = make_float4(0.f, 0.f, 0.f, 0.f);
#pragma unroll
    for (int p = 0; p < NSPLIT; p++) {
        const float fp = __expf(pm[p] - M);
        const float4 v =
            __ldcg((const float4*)(g_acc + (size_t)(b * NSPLIT + p) * D) + d4);
        a.x = fmaf(fp, v.x, a.x);
        a.y = fmaf(fp, v.y, a.y);
        a.z = fmaf(fp, v.z, a.z);
        a.w = fmaf(fp, v.w, a.w);
    }
    a.x *= Linv; a.y *= Linv; a.z *= Linv; a.w *= Linv;
    ((float4*)(out + (size_t)b * D))[d4] = a;

    if (threadIdx.x == 0) atomicExch(&g_cnt[b], 0);
}

extern "C" void kernel_launch(void* const* d_in, const int* in_sizes, int n_in,
                              void* d_out, int out_size)
{
    const float* target  = (const float*)d_in[0];  // [B, D]
    const float* context = (const float*)d_in[1];  // [B, S, D]
    const float* mask    = (const float*)d_in[2];  // [B, S]
    float* out = (float*)d_out;                    // [B, D]

    cudaFuncSetAttribute(attn_fused,
                         cudaFuncAttributeMaxDynamicSharedMemorySize,
                         STAGE_BYTES);

    dim3 grid(B, NSPLIT);
    attn_fused<<<grid, THREADS, STAGE_BYTES>>>(target, context, mask, out);
}

// round 7
// speedup vs baseline: 2.2358x; 1.6578x over previous
#include <cuda_runtime.h>
#include <math.h>

// Problem constants
#define B 32
#define S 2048
#define D 1024
#define MASK_PENALTY 100000000.0f

// Tiling
#define NSPLIT 8
#define WARPS 8
#define THREADS (WARPS * 32)
#define ROWS_PER_SPLIT (S / NSPLIT)             // 256
#define ROWS_PER_WARP (ROWS_PER_SPLIT / WARPS)  // 32 (== warp size, mask preload)

// Scratch (allocation-free: __device__ globals, zero-init)
__device__ float g_m[B * NSPLIT];
__device__ float g_l[B * NSPLIT];
__device__ __align__(16) float g_acc[(size_t)B * NSPLIT * D];  // 1 MB
__device__ int g_cnt[B];  // zero-init; self-resets each launch

// ---------------------------------------------------------------------------
// Fused single-pass online-softmax attention WITH MASK SKIPPING.
// Masked rows (mask==0) contribute exp(-1e8)==0.0f exactly in fp32, so we
// skip their 4KB loads entirely (warp-uniform branch, no divergence).
// One warp per context row; each lane owns 32 of 1024 D-elements
// (8 x float4 at element offset 4*(lane + 32*i), fully coalesced).
// 8 warp partials merge in smem -> 1 per CTA -> last CTA per batch merges.
// ---------------------------------------------------------------------------
__global__ void __launch_bounds__(THREADS)
attn_fused(const float* __restrict__ target,
           const float* __restrict__ context,
           const float* __restrict__ mask,
           float* __restrict__ out)
{
    const int b     = blockIdx.x;
    const int split = blockIdx.y;
    const int w     = threadIdx.x >> 5;
    const int lane  = threadIdx.x & 31;

    // Lane's slice of the query vector (registers)
    const float4* tg = (const float4*)(target + (size_t)b * D);
    float4 t[8];
#pragma unroll
    for (int i = 0; i < 8; i++) t[i] = tg[lane + 32 * i];

    float4 acc[8];
#pragma unroll
    for (int i = 0; i < 8; i++) acc[i] = make_float4(0.f, 0.f, 0.f, 0.f);

    float m = -INFINITY;
    float l = 0.f;

    const int s0 = split * ROWS_PER_SPLIT + w * ROWS_PER_WARP;
    const float* cb = context + (size_t)b * S * D;

    // Preload this warp's 32 masks (one per lane); build a ballot of valid rows
    const float mkv = mask[(size_t)b * S + s0 + lane];
    const unsigned valid = __ballot_sync(0xffffffffu, mkv != 0.f);

    for (int r = 0; r < ROWS_PER_WARP; r++) {
        // Skip masked rows entirely: their softmax weight is exactly 0.
        if (!((valid >> r) & 1u)) continue;

        const float4* row = (const float4*)(cb + (size_t)(s0 + r) * D);

        float4 c[8];
#pragma unroll
        for (int i = 0; i < 8; i++) c[i] = row[lane + 32 * i];

        // dot(context_row, target) for this lane's slice (2 chains)
        float d0 = 0.f, d1 = 0.f;
#pragma unroll
        for (int i = 0; i < 8; i++) {
            d0 = fmaf(c[i].x, t[i].x, d0);
            d1 = fmaf(c[i].y, t[i].y, d1);
            d0 = fmaf(c[i].z, t[i].z, d0);
            d1 = fmaf(c[i].w, t[i].w, d1);
        }
        float dot = d0 + d1;
#pragma unroll
        for (int off = 16; off > 0; off >>= 1)
            dot += __shfl_xor_sync(0xffffffffu, dot, off);

        // valid row => mask==1 => penalty term is 0; score = dot
        const float score = dot;

        // online softmax update
        const float mnew  = fmaxf(m, score);
        const float scale = __expf(m - mnew);     // 0 on first valid row
        const float wgt   = __expf(score - mnew);
        l = l * scale + wgt;
#pragma unroll
        for (int i = 0; i < 8; i++) {
            acc[i].x = fmaf(acc[i].x, scale, wgt * c[i].x);
            acc[i].y = fmaf(acc[i].y, scale, wgt * c[i].y);
            acc[i].z = fmaf(acc[i].z, scale, wgt * c[i].z);
            acc[i].w = fmaf(acc[i].w, scale, wgt * c[i].w);
        }
        m = mnew;
    }

    // ---- In-CTA merge of the 8 warp partials ----
    __shared__ float sm_[WARPS];
    __shared__ float sl_[WARPS];
    __shared__ __align__(16) float4 sacc[WARPS][D / 4];   // 32 KB

    if (lane == 0) { sm_[w] = m; sl_[w] = l; }
    __syncthreads();

    float Mcta = -INFINITY;
#pragma unroll
    for (int i = 0; i < WARPS; i++) Mcta = fmaxf(Mcta, sm_[i]);

    // Guard: warp with zero valid rows has m=-inf (and possibly Mcta=-inf).
    const float f = (m > -INFINITY) ? __expf(m - Mcta) : 0.f;
#pragma unroll
    for (int i = 0; i < 8; i++) {
        float4 a = acc[i];
        a.x *= f; a.y *= f; a.z *= f; a.w *= f;
        sacc[w][lane + 32 * i] = a;
    }
    __syncthreads();

    // 256 threads sum across the 8 warps, write CTA partial
    const int pidx = b * NSPLIT + split;
    const int d4 = threadIdx.x;
    float4 sum = sacc[0][d4];
#pragma unroll
    for (int i = 1; i < WARPS; i++) {
        const float4 v = sacc[i][d4];
        sum.x += v.x; sum.y += v.y; sum.z += v.z; sum.w += v.w;
    }
    ((float4*)(g_acc + (size_t)pidx * D))[d4] = sum;

    if (threadIdx.x == 0) {
        float L = 0.f;
#pragma unroll
        for (int i = 0; i < WARPS; i++)
            L += (sm_[i] > -INFINITY ? __expf(sm_[i] - Mcta) : 0.f) * sl_[i];
        g_m[pidx] = Mcta;   // may be -inf if the whole split is masked
        g_l[pidx] = L;
    }

    // ---- Last CTA per batch merges the NSPLIT partials ----
    __threadfence();
    __syncthreads();
    __shared__ int isLast;
    if (threadIdx.x == 0)
        isLast = (atomicAdd(&g_cnt[b], 1) == NSPLIT - 1);
    __syncthreads();
    if (!isLast) return;
    __threadfence();  // acquire

    float pm[NSPLIT], pl[NSPLIT];
#pragma unroll
    for (int p = 0; p < NSPLIT; p++) {
        pm[p] = __ldcg(&g_m[b * NSPLIT + p]);
        pl[p] = __ldcg(&g_l[b * NSPLIT + p]);
    }
    // M is finite: position 0 of every batch is guaranteed valid.
    float M = -INFINITY;
#pragma unroll
    for (int p = 0; p < NSPLIT; p++) M = fmaxf(M, pm[p]);
    float L = 0.f;
#pragma unroll
    for (int p = 0; p < NSPLIT; p++)
        L += (pm[p] > -INFINITY ? __expf(pm[p] - M) : 0.f) * pl[p];
    const float Linv = 1.f / L;

    float4 a = make_float4(0.f, 0.f, 0.f, 0.f);
#pragma unroll
    for (int p = 0; p < NSPLIT; p++) {
        const float fp = (pm[p] > -INFINITY) ? __expf(pm[p] - M) : 0.f;
        const float4 v =
            __ldcg((const float4*)(g_acc + (size_t)(b * NSPLIT + p) * D) + d4);
        a.x = fmaf(fp, v.x, a.x);
        a.y = fmaf(fp, v.y, a.y);
        a.z = fmaf(fp, v.z, a.z);
        a.w = fmaf(fp, v.w, a.w);
    }
    a.x *= Linv; a.y *= Linv; a.z *= Linv; a.w *= Linv;
    ((float4*)(out + (size_t)b * D))[d4] = a;

    if (threadIdx.x == 0) atomicExch(&g_cnt[b], 0);
}

extern "C" void kernel_launch(void* const* d_in, const int* in_sizes, int n_in,
                              void* d_out, int out_size)
{
    const float* target  = (const float*)d_in[0];  // [B, D]
    const float* context = (const float*)d_in[1];  // [B, S, D]
    const float* mask    = (const float*)d_in[2];  // [B, S]
    float* out = (float*)d_out;                    // [B, D]

    dim3 grid(B, NSPLIT);
    attn_fused<<<grid, THREADS>>>(target, context, mask, out);
}